// round 15
// baseline (speedup 1.0000x reference)
#include <cuda_runtime.h>
#include <cstdint>

// Problem constants
#define Gn 4
#define Kn 1024
#define Dn 64
#define NPG 32768                 // rows (B*T) per group
#define TPB 256                   // threads per block, 1 row per thread
#define TILES_PER_G (NPG / TPB)   // 128
#define KC 256                    // codewords per smem chunk
#define NCHUNK (Kn / KC)          // 4
#define KT 8                      // codewords per register tile
#define NELEM 8388608ULL          // B*T*G*D total latent elements

__device__ double g_loss;
__device__ float  g_csq[Gn * Kn];

// Packed fp32x2 FMA (sm_100+): two independent fused fp32 FMAs per instruction.
// Exact-fp32 dot (NO operand conversion this round). Accumulation-order noise
// vs the reference GEMM ~1e-9, below the joint knife-edge*tie sensitivity
// (~1e-6/row) of the coarse argmin -> ~0 expected flips.
__device__ __forceinline__ unsigned long long fma2(unsigned long long a,
                                                   unsigned long long b,
                                                   unsigned long long c) {
    unsigned long long r;
    asm("fma.rn.f32x2 %0, %1, %2, %3;" : "=l"(r) : "l"(a), "l"(b), "l"(c));
    return r;
}

__device__ __forceinline__ float lo_f(unsigned long long v) {
    return __uint_as_float((unsigned)(v & 0xffffffffULL));
}
__device__ __forceinline__ float hi_f(unsigned long long v) {
    return __uint_as_float((unsigned)(v >> 32));
}

// Init: zero loss accumulator, precompute per-codeword squared norms.
__global__ void vq_init(const float* __restrict__ cb) {
    int idx = blockIdx.x * blockDim.x + threadIdx.x;
    if (idx == 0) g_loss = 0.0;
    if (idx < Gn * Kn) {
        const float* row = cb + (size_t)idx * Dn;
        float s = 0.f;
#pragma unroll
        for (int d = 0; d < Dn; d++) s = fmaf(row[d], row[d], s);
        g_csq[idx] = s;
    }
}

extern __shared__ float s_dyn[];

// Main: per thread one latent row.
// R15 model — the untested grid cell (EXACT dot, COARSE score):
//   X     = x_sq (adjacent-pair tree; low bits shift all scores by exact
//           grid multiples -> argmin-invariant)
//   e_k   = EXACT fp32 dot (no tf32 conversion), fused FMA accumulation
//   dist  = fl( fl(X - 2*e_k) + csq_k )   (left-to-right, as the python expr)
//   argmin: ascending k, strict <  (first-index tie-break == jnp.argmin)
//   out   = fl(x + fl(q - x))  (straight-through estimator rounding)
__global__ __launch_bounds__(TPB, 2)
void vq_main(const float* __restrict__ lat,
             const float* __restrict__ cb,
             float* __restrict__ out) {
    float* s_cs  = s_dyn;                  // KC * Dn floats (codebook chunk, raw fp32)
    float* s_csq = s_dyn + KC * Dn;        // KC floats
    float* s_red = s_csq + KC;             // 32 floats (reduction)

    const int g    = blockIdx.x >> 7;                 // TILES_PER_G = 128
    const int tile = blockIdx.x & (TILES_PER_G - 1);
    const int n    = tile * TPB + threadIdx.x;        // row within group

    const float* xrow = lat + (size_t)n * (Gn * Dn) + (size_t)g * Dn;

    // Load row x packed as 32 f32x2 (64 regs) — raw fp32, no conversion.
    unsigned long long x2[Dn / 2];
    {
        const ulonglong2* xp = (const ulonglong2*)xrow;
#pragma unroll
        for (int i = 0; i < Dn / 4; i++) {
            ulonglong2 v = xp[i];
            x2[2 * i]     = v.x;
            x2[2 * i + 1] = v.y;
        }
    }

    // X = x_sq (sequential-pair tree; low-bit differences cannot affect argmin).
    float X;
    {
        float p[32];
#pragma unroll
        for (int i = 0; i < 32; i++) {
            float a = lo_f(x2[i]), b = hi_f(x2[i]);
            p[i] = __fadd_rn(__fmul_rn(a, a), __fmul_rn(b, b));
        }
#pragma unroll
        for (int off = 16; off; off >>= 1)
#pragma unroll
            for (int t = 0; t < 16; t++)
                if (t < off) p[t] = __fadd_rn(p[t], p[t + off]);
        X = p[0];
    }

    const float* cbg = cb + (size_t)g * Kn * Dn;

    float best  = 3.4e38f;
    int   bestk = 0;

    for (int ch = 0; ch < NCHUNK; ch++) {
        __syncthreads();
        // Stage codebook chunk (raw fp32) + csq into smem (coalesced float4).
        {
            const float4* src = (const float4*)(cbg + (size_t)ch * KC * Dn);
            float4*       dst = (float4*)s_cs;
#pragma unroll
            for (int i = threadIdx.x; i < KC * Dn / 4; i += TPB) dst[i] = src[i];
            if (threadIdx.x < KC)
                s_csq[threadIdx.x] = g_csq[g * Kn + ch * KC + threadIdx.x];
        }
        __syncthreads();

        const ulonglong2* cs2 = (const ulonglong2*)s_cs;  // 16 ulonglong2 per k row

        for (int kt = 0; kt < KC; kt += KT) {
            unsigned long long acc[KT];
#pragma unroll
            for (int j = 0; j < KT; j++) acc[j] = 0ULL;

            const ulonglong2* crow = cs2 + (size_t)kt * (Dn / 4);
#pragma unroll
            for (int d4 = 0; d4 < Dn / 4; d4++) {
                unsigned long long xa = x2[2 * d4];
                unsigned long long xb = x2[2 * d4 + 1];
#pragma unroll
                for (int j = 0; j < KT; j++) {
                    ulonglong2 c = crow[j * (Dn / 4) + d4];  // LDS.128, broadcast
                    acc[j] = fma2(xa, c.x, acc[j]);
                    acc[j] = fma2(xb, c.y, acc[j]);
                }
            }
#pragma unroll
            for (int j = 0; j < KT; j++) {
                float dot   = __fadd_rn(lo_f(acc[j]), hi_f(acc[j]));
                // Coarse score: dist = fl( fl(X - 2*dot) + csq )
                float t1    = __fsub_rn(X, 2.0f * dot);
                float score = __fadd_rn(t1, s_csq[kt + j]);
                int   kk    = ch * KC + kt + j;
                if (score < best) { best = score; bestk = kk; }  // strict <: first index on ties
            }
        }
    }

    // Gather winning codeword, emulate STE rounding, accumulate exact (q-x)^2.
    float dist = 0.f;
    {
        const float4* qsrc = (const float4*)(cbg + (size_t)bestk * Dn);
        float4* orow = (float4*)(out + (size_t)n * (Gn * Dn) + (size_t)g * Dn);
#pragma unroll
        for (int i = 0; i < Dn / 4; i++) {
            float4 q = __ldg(&qsrc[i]);
            float x0 = lo_f(x2[2 * i]);
            float x1 = hi_f(x2[2 * i]);
            float x2v = lo_f(x2[2 * i + 1]);
            float x3 = hi_f(x2[2 * i + 1]);
            float d0 = __fsub_rn(q.x, x0);
            float d1 = __fsub_rn(q.y, x1);
            float d2 = __fsub_rn(q.z, x2v);
            float d3 = __fsub_rn(q.w, x3);
            float4 o;
            o.x = __fadd_rn(x0, d0);
            o.y = __fadd_rn(x1, d1);
            o.z = __fadd_rn(x2v, d2);
            o.w = __fadd_rn(x3, d3);
            orow[i] = o;
            dist = fmaf(d0, d0, dist);
            dist = fmaf(d1, d1, dist);
            dist = fmaf(d2, d2, dist);
            dist = fmaf(d3, d3, dist);
        }
    }

    // Block reduction of dist, then one double atomicAdd per CTA.
#pragma unroll
    for (int off = 16; off; off >>= 1)
        dist += __shfl_down_sync(0xffffffffu, dist, off);
    int lane = threadIdx.x & 31;
    int wid  = threadIdx.x >> 5;
    if (lane == 0) s_red[wid] = dist;
    __syncthreads();
    if (wid == 0) {
        float v = (lane < TPB / 32) ? s_red[lane] : 0.f;
#pragma unroll
        for (int off = 4; off; off >>= 1)
            v += __shfl_down_sync(0xffffffffu, v, off);
        if (lane == 0) atomicAdd(&g_loss, (double)v);
    }
}

// Finalize: vq_loss = (1 + BETA) * mean((q - x)^2), BETA = 0.25.
__global__ void vq_fin(float* out, int out_size) {
    out[out_size - 1] = (float)(g_loss * 1.25 / (double)NELEM);
}

extern "C" void kernel_launch(void* const* d_in, const int* in_sizes, int n_in,
                              void* d_out, int out_size) {
    const float* lat = (const float*)d_in[0];   // latents  [32768, 256] fp32
    const float* cb  = (const float*)d_in[1];   // codebooks [4, 1024, 64] fp32
    float* out = (float*)d_out;

    size_t smem = (size_t)(KC * Dn + KC + 32) * sizeof(float);  // ~66.7 KB
    cudaFuncSetAttribute(vq_main, cudaFuncAttributeMaxDynamicSharedMemorySize,
                         (int)smem);

    vq_init<<<(Gn * Kn + 255) / 256, 256>>>(cb);
    vq_main<<<Gn * TILES_PER_G, TPB, smem>>>(lat, cb, out);
    vq_fin<<<1, 1>>>(out, out_size);
}

// round 17
// speedup vs baseline: 1.6216x; 1.6216x over previous
#include <cuda_runtime.h>
#include <cstdint>

// Problem constants
#define Gn 4
#define Kn 1024
#define Dn 64
#define NPG 32768                    // rows (B*T) per group
#define TPB 256                      // 8 warps
#define ROWS_PER_CTA 128             // 8 warps * m16
#define MTILES (NPG / ROWS_PER_CTA)  // 256
#define KC 128                       // codewords per smem chunk
#define NCHUNK (Kn / KC)             // 8
#define SB2 36                       // float2 stride per k-row (bank-conflict-free: 36 mod 16 == 4)
#define MARGIN 4e-4f                 // >= 2E_tf32 + 2*coarse_bin, 2x headroom
#define NELEM 8388608ULL

__device__ double g_loss;
__device__ float  g_csq[Gn * Kn];
__device__ float  g_xsq[Gn * NPG];

__device__ __forceinline__ unsigned tf32_rna(float x) {
    unsigned r;
    asm("cvt.rna.tf32.f32 %0, %1;" : "=r"(r) : "f"(x));
    return r;
}

// m16n8k8 tf32 HMMA, fp32 accumulate (fragment geometry validated in R13).
__device__ __forceinline__ void mma_tf32(float acc[4],
                                         const unsigned a[4],
                                         unsigned b0, unsigned b1) {
    asm volatile(
        "mma.sync.aligned.m16n8k8.row.col.f32.tf32.tf32.f32 "
        "{%0,%1,%2,%3}, {%4,%5,%6,%7}, {%8,%9}, {%0,%1,%2,%3};"
        : "+f"(acc[0]), "+f"(acc[1]), "+f"(acc[2]), "+f"(acc[3])
        : "r"(a[0]), "r"(a[1]), "r"(a[2]), "r"(a[3]), "r"(b0), "r"(b1));
}

// Top-3 insertion, all indices static (stays in registers).
__device__ __forceinline__ void ins3(float cs[3], int ci[3], float y, int k) {
    if (y < cs[2]) {
        cs[2] = y; ci[2] = k;
        if (cs[2] < cs[1]) { float t = cs[1]; cs[1] = cs[2]; cs[2] = t;
                             int ti = ci[1]; ci[1] = ci[2]; ci[2] = ti; }
        if (cs[1] < cs[0]) { float t = cs[0]; cs[0] = cs[1]; cs[1] = t;
                             int ti = ci[0]; ci[0] = ci[1]; ci[1] = ti; }
    }
}

// Exact rescore — BIT-IDENTICAL to the R15 passing pipeline:
// even/odd-split fused-FMA dot, then fl( fl(X - 2e) + csq ).
__device__ __forceinline__ float exact_score(const float* __restrict__ x,
                                             const float* __restrict__ c,
                                             float X, float csq) {
    float elo = 0.f, ehi = 0.f;
#pragma unroll
    for (int i = 0; i < Dn / 2; i++) {
        elo = fmaf(__ldg(x + 2 * i),     __ldg(c + 2 * i),     elo);
        ehi = fmaf(__ldg(x + 2 * i + 1), __ldg(c + 2 * i + 1), ehi);
    }
    float e = __fadd_rn(elo, ehi);
    return __fadd_rn(__fsub_rn(X, 2.0f * e), csq);
}

// Pre-pass: zero loss, codeword norms, per-row x_sq (identical to R15's X:
// adjacent-pair seeding + offsets 16..1 tree).
__global__ void vq_pre(const float* __restrict__ lat,
                       const float* __restrict__ cb) {
    int idx = blockIdx.x * blockDim.x + threadIdx.x;
    if (idx == 0) g_loss = 0.0;
    if (idx < Gn * Kn) {
        const float* row = cb + (size_t)idx * Dn;
        float s = 0.f;
#pragma unroll
        for (int d = 0; d < Dn; d++) s = fmaf(row[d], row[d], s);
        g_csq[idx] = s;
    }
    if (idx < Gn * NPG) {
        int n = idx >> 2, g = idx & 3;
        const float* x = lat + (size_t)n * (Gn * Dn) + (size_t)g * Dn;
        float p[32];
#pragma unroll
        for (int i = 0; i < 32; i++)
            p[i] = __fadd_rn(__fmul_rn(x[2 * i], x[2 * i]),
                             __fmul_rn(x[2 * i + 1], x[2 * i + 1]));
#pragma unroll
        for (int off = 16; off; off >>= 1)
#pragma unroll
            for (int t = 0; t < 16; t++)
                if (t < off) p[t] = __fadd_rn(p[t], p[t + off]);
        g_xsq[g * NPG + n] = p[0];
    }
}

extern __shared__ float s_dyn[];

__global__ __launch_bounds__(TPB, 2)
void vq_main(const float* __restrict__ lat,
             const float* __restrict__ cb,
             float* __restrict__ out) {
    float* s_b   = s_dyn;                       // KC*SB2 float2 (HMMA-native B layout)
    float* s_csq = s_dyn + KC * SB2 * 2;        // KC floats
    float* s_red = s_csq + KC;                  // 32 floats

    const int g    = blockIdx.y;
    const int tid  = threadIdx.x;
    const int w    = tid >> 5;
    const int lane = tid & 31;
    const int lq   = lane >> 2;                 // 0..7
    const int lr   = lane & 3;                  // 0..3

    const int r0 = blockIdx.x * ROWS_PER_CTA + w * 16 + lq;
    const int r1 = r0 + 8;

    const float* x0p = lat + (size_t)r0 * (Gn * Dn) + (size_t)g * Dn;
    const float* x1p = lat + (size_t)r1 * (Gn * Dn) + (size_t)g * Dn;

    // A fragments (single tf32 plane — approximate pass).
    unsigned a[8][4];
#pragma unroll
    for (int d = 0; d < 8; d++) {
        int c = d * 8 + lr;
        a[d][0] = tf32_rna(__ldg(x0p + c));
        a[d][1] = tf32_rna(__ldg(x1p + c));
        a[d][2] = tf32_rna(__ldg(x0p + c + 4));
        a[d][3] = tf32_rna(__ldg(x1p + c + 4));
    }

    // Per-lane top-3 candidates (fine approx score, global-in-group index).
    float cs0[3] = {3.4e38f, 3.4e38f, 3.4e38f};
    float cs1[3] = {3.4e38f, 3.4e38f, 3.4e38f};
    int   ci0[3] = {0, 0, 0};
    int   ci1[3] = {0, 0, 0};

    const float* cbg = cb + (size_t)g * Kn * Dn;

    for (int ch = 0; ch < NCHUNK; ch++) {
        __syncthreads();
        // Stage codebook chunk in HMMA-native float2 layout:
        // slot (k*SB2 + d*4 + lr) holds {c[k][d*8+lr], c[k][d*8+lr+4]}.
        {
            const float4* src = (const float4*)(cbg + (size_t)ch * KC * Dn);
            for (int i = tid; i < KC * 16; i += TPB) {
                int k = i >> 4, dq = i & 15;
                float4 v = src[i];
#pragma unroll
                for (int e = 0; e < 4; e++) {
                    int col = dq * 4 + e;
                    float val = (e == 0) ? v.x : (e == 1) ? v.y : (e == 2) ? v.z : v.w;
                    int d = col >> 3, wi = col & 7;
                    int slot = k * SB2 + d * 4 + (wi & 3);
                    s_b[slot * 2 + (wi >> 2)] = __uint_as_float(tf32_rna(val));
                }
            }
            if (tid < KC) s_csq[tid] = g_csq[g * Kn + ch * KC + tid];
        }
        __syncthreads();

        const float2* bp = (const float2*)s_b;
        for (int kt = 0; kt < KC / 8; kt++) {
            float acc[4] = {0.f, 0.f, 0.f, 0.f};
            const float2* brow = bp + (size_t)(kt * 8 + lq) * SB2 + lr;
#pragma unroll
            for (int d = 0; d < 8; d++) {
                float2 b = brow[d * 4];                 // LDS.64, conflict-free
                mma_tf32(acc, a[d], __float_as_uint(b.x), __float_as_uint(b.y));
            }
            int   k0  = ch * KC + kt * 8 + 2 * lr;
            float q0  = s_csq[kt * 8 + 2 * lr];
            float q1  = s_csq[kt * 8 + 2 * lr + 1];
            ins3(cs0, ci0, fmaf(-2.f, acc[0], q0), k0);
            ins3(cs0, ci0, fmaf(-2.f, acc[1], q1), k0 + 1);
            ins3(cs1, ci1, fmaf(-2.f, acc[2], q0), k0);
            ins3(cs1, ci1, fmaf(-2.f, acc[3], q1), k0 + 1);
        }
    }

    // Global approx min per row (across the 4 lanes sharing it).
    float gb0 = cs0[0], gb1 = cs1[0];
#pragma unroll
    for (int off = 1; off <= 2; off <<= 1) {
        gb0 = fminf(gb0, __shfl_xor_sync(0xffffffffu, gb0, off));
        gb1 = fminf(gb1, __shfl_xor_sync(0xffffffffu, gb1, off));
    }
    const float thr0 = gb0 + MARGIN, thr1 = gb1 + MARGIN;

    // Exact rescore of margin-passing candidates (R15-bit-exact numerics).
    const float X0 = g_xsq[g * NPG + r0];
    const float X1 = g_xsq[g * NPG + r1];
    float se0 = 3.4e38f, se1 = 3.4e38f;
    int   ke0 = 0x7fffffff, ke1 = 0x7fffffff;
#pragma unroll
    for (int s = 0; s < 3; s++) {
        if (cs0[s] <= thr0) {
            int k = ci0[s];
            float sc = exact_score(x0p, cbg + (size_t)k * Dn, X0, g_csq[g * Kn + k]);
            if (sc < se0 || (sc == se0 && k < ke0)) { se0 = sc; ke0 = k; }
        }
        if (cs1[s] <= thr1) {
            int k = ci1[s];
            float sc = exact_score(x1p, cbg + (size_t)k * Dn, X1, g_csq[g * Kn + k]);
            if (sc < se1 || (sc == se1 && k < ke1)) { se1 = sc; ke1 = k; }
        }
    }
    // Cross-lane lexicographic (score, index) reduce == first-index argmin.
#pragma unroll
    for (int off = 1; off <= 2; off <<= 1) {
        float os = __shfl_xor_sync(0xffffffffu, se0, off);
        int   oi = __shfl_xor_sync(0xffffffffu, ke0, off);
        if (os < se0 || (os == se0 && oi < ke0)) { se0 = os; ke0 = oi; }
        os = __shfl_xor_sync(0xffffffffu, se1, off);
        oi = __shfl_xor_sync(0xffffffffu, ke1, off);
        if (os < se1 || (os == se1 && oi < ke1)) { se1 = os; ke1 = oi; }
    }

    // Winner: STE rounding out = fl(x + fl(q - x)); exact (q-x)^2 for loss.
    float dist = 0.f;
    if (lr == 0) {
#pragma unroll
        for (int half = 0; half < 2; half++) {
            int row = half ? r1 : r0;
            int bk  = half ? ke1 : ke0;
            const float4* qsrc = (const float4*)(cbg + (size_t)bk * Dn);
            const float4* xsrc = (const float4*)(half ? x1p : x0p);
            float4* orow = (float4*)(out + (size_t)row * (Gn * Dn) + (size_t)g * Dn);
#pragma unroll
            for (int i = 0; i < Dn / 4; i++) {
                float4 q = __ldg(&qsrc[i]);
                float4 x = __ldg(&xsrc[i]);
                float d0 = __fsub_rn(q.x, x.x);
                float d1 = __fsub_rn(q.y, x.y);
                float d2 = __fsub_rn(q.z, x.z);
                float d3 = __fsub_rn(q.w, x.w);
                float4 o;
                o.x = __fadd_rn(x.x, d0);
                o.y = __fadd_rn(x.y, d1);
                o.z = __fadd_rn(x.z, d2);
                o.w = __fadd_rn(x.w, d3);
                orow[i] = o;
                dist = fmaf(d0, d0, dist);
                dist = fmaf(d1, d1, dist);
                dist = fmaf(d2, d2, dist);
                dist = fmaf(d3, d3, dist);
            }
        }
    }

    // Block reduce, one double atomicAdd per CTA.
#pragma unroll
    for (int off = 16; off; off >>= 1)
        dist += __shfl_down_sync(0xffffffffu, dist, off);
    if (lane == 0) s_red[w] = dist;
    __syncthreads();
    if (w == 0) {
        float v = (lane < TPB / 32) ? s_red[lane] : 0.f;
#pragma unroll
        for (int off = 4; off; off >>= 1)
            v += __shfl_down_sync(0xffffffffu, v, off);
        if (lane == 0) atomicAdd(&g_loss, (double)v);
    }
}

// Finalize: vq_loss = (1 + BETA) * mean((q - x)^2), BETA = 0.25.
__global__ void vq_fin(float* out, int out_size) {
    out[out_size - 1] = (float)(g_loss * 1.25 / (double)NELEM);
}

extern "C" void kernel_launch(void* const* d_in, const int* in_sizes, int n_in,
                              void* d_out, int out_size) {
    const float* lat = (const float*)d_in[0];   // latents  [32768, 256] fp32
    const float* cb  = (const float*)d_in[1];   // codebooks [4, 1024, 64] fp32
    float* out = (float*)d_out;

    size_t smem = (size_t)(KC * SB2 * 2 + KC + 32) * sizeof(float);  // ~37.5 KB
    cudaFuncSetAttribute(vq_main, cudaFuncAttributeMaxDynamicSharedMemorySize,
                         (int)smem);

    vq_pre<<<(Gn * NPG + TPB - 1) / TPB, TPB>>>(lat, cb);
    dim3 grid(MTILES, Gn);
    vq_main<<<grid, TPB, smem>>>(lat, cb, out);
    vq_fin<<<1, 1>>>(out, out_size);
}